// round 16
// baseline (speedup 1.0000x reference)
#include <cuda_runtime.h>
#include <cstdint>

#define CD 512
#define KD 65536
#define BM 128
#define BK 64
#define NPAIRS 10
#define SPLITS 14
#define NCHUNK (KD / BK)             // 1024
#define NSLOT 3
#define THREADS 384                  // 8 consumer + 4 producer warps
#define WSTRIDE 36                   // words per smem row (frag LDS conflict-free)
#define TILE_W (BM * WSTRIDE)
#define STAGE_W (2 * TILE_W)
#define SMEM_BYTES (NSLOT * STAGE_W * 4)   // 110592 B -> 1 CTA/SM

// Deterministic split-K partial planes (no device allocation allowed)
__device__ float g_part[(size_t)NPAIRS * SPLITS * 16384];

__device__ __forceinline__ uint32_t s2u(const void* p) {
    uint32_t a;
    asm("{ .reg .u64 t; cvta.to.shared.u64 t, %1; cvt.u32.u64 %0, t; }" : "=r"(a) : "l"(p));
    return a;
}
__device__ __forceinline__ uint32_t bf2(float x, float y) {
    uint32_t r;
    asm("cvt.rn.bf16x2.f32 %0, %1, %2;" : "=r"(r) : "f"(y), "f"(x));
    return r;
}
__device__ __forceinline__ void sts64(uint32_t a, uint32_t w0, uint32_t w1) {
    asm volatile("st.shared.v2.b32 [%0], {%1, %2};" :: "r"(a), "r"(w0), "r"(w1) : "memory");
}
__device__ __forceinline__ void bar_wait(int id) {
    asm volatile("bar.sync %0, 384;" :: "r"(id) : "memory");
}
__device__ __forceinline__ void bar_post(int id) {
    asm volatile("bar.arrive %0, 384;" :: "r"(id) : "memory");
}

__global__ __launch_bounds__(THREADS, 1) void gram_fused(const float* __restrict__ X) {
    extern __shared__ uint32_t smw[];
    const uint32_t sb = s2u(smw);

    const int pair  = blockIdx.x % NPAIRS;
    const int split = blockIdx.x / NPAIRS;

    int bi = 0;
    while ((bi + 1) * (bi + 2) / 2 <= pair) bi++;
    const int bj = pair - bi * (bi + 1) / 2;
    const bool diag = (bi == bj);

    const int c0 = (split * NCHUNK) / SPLITS;
    const int c1 = ((split + 1) * NCHUNK) / SPLITS;
    const int niters = c1 - c0;

    const int tid  = threadIdx.x;
    const int lane = tid & 31;
    const int wid  = tid >> 5;

    if (wid >= 8) {
        // ============ producers (warps 8-11): fp32 LDG -> cvt -> STS (as R12) ============
        const int pu    = tid - 256;        // 0..127
        const int ptile = pu >> 6;          // 0 = A tile, 1 = B tile
        const int pv    = pu & 63;
        const int pg    = pv & 15;          // float4 granule: k = 4*pg .. 4*pg+3
        const int prb   = pv >> 4;          // row base 0..3 (rows prb + 4*kidx)
        const bool skip = diag && (ptile == 1);
        const uint32_t tile_w = (uint32_t)(ptile ? TILE_W : 0);
        const float* gp = X + (size_t)((ptile ? bj : bi) * BM + prb) * KD + 4 * pg;

        for (int i = 0; i < niters; i++) {
            const int s = i % NSLOT;
            if (i >= NSLOT) bar_wait(4 + s);          // wait slot empty
            if (!skip) {
                const float* g = gp + (size_t)(c0 + i) * BK;
                const uint32_t base = sb + (uint32_t)(s * STAGE_W + tile_w) * 4u;
                #pragma unroll
                for (int b = 0; b < 2; b++) {
                    float4 v[16];
                    #pragma unroll
                    for (int k = 0; k < 16; k++)
                        v[k] = *(const float4*)(g + (size_t)(4 * (16 * b + k)) * KD);
                    #pragma unroll
                    for (int k = 0; k < 16; k++) {
                        const int row = prb + 4 * (16 * b + k);
                        sts64(base + (uint32_t)(row * WSTRIDE + 2 * pg) * 4u,
                              bf2(v[k].x, v[k].y), bf2(v[k].z, v[k].w));
                    }
                }
            }
            bar_post(1 + s);                          // signal slot full
        }
        return;
    }

    // ============ consumers (warps 0-7, 2 per SMSP): bf16 m16n8k16 mma ============
    const int wr = wid >> 2;            // 0..1 -> rows 64*wr
    const int wc = wid & 3;             // 0..3 -> cols 32*wc
    const int g  = lane >> 2;           // 0..7
    const int t  = lane & 3;            // 0..3

    float acc[4][4][4];
    #pragma unroll
    for (int mi = 0; mi < 4; mi++)
        #pragma unroll
        for (int ni = 0; ni < 4; ni++)
            #pragma unroll
            for (int e = 0; e < 4; e++) acc[mi][ni][e] = 0.f;

    for (int i = 0; i < niters; i++) {
        const int s = i % NSLOT;
        bar_wait(1 + s);                              // wait slot full

        const uint32_t* As = smw + s * STAGE_W;
        const uint32_t* Bs = diag ? As : (As + TILE_W);

        #pragma unroll
        for (int kk = 0; kk < 4; kk++) {
            const int kw = kk * 8 + t;
            uint32_t ar[4][4];
            #pragma unroll
            for (int mi = 0; mi < 4; mi++) {
                const int r = 64 * wr + 16 * mi + g;
                ar[mi][0] = As[r * WSTRIDE + kw];
                ar[mi][1] = As[(r + 8) * WSTRIDE + kw];
                ar[mi][2] = As[r * WSTRIDE + kw + 4];
                ar[mi][3] = As[(r + 8) * WSTRIDE + kw + 4];
            }
            uint32_t br[4][2];
            #pragma unroll
            for (int ni = 0; ni < 4; ni++) {
                const int n = 32 * wc + 8 * ni + g;
                br[ni][0] = Bs[n * WSTRIDE + kw];
                br[ni][1] = Bs[n * WSTRIDE + kw + 4];
            }
            #pragma unroll
            for (int mi = 0; mi < 4; mi++)
                #pragma unroll
                for (int ni = 0; ni < 4; ni++) {
                    asm volatile(
                        "mma.sync.aligned.m16n8k16.row.col.f32.bf16.bf16.f32 "
                        "{%0,%1,%2,%3}, {%4,%5,%6,%7}, {%8,%9}, {%0,%1,%2,%3};"
                        : "+f"(acc[mi][ni][0]), "+f"(acc[mi][ni][1]),
                          "+f"(acc[mi][ni][2]), "+f"(acc[mi][ni][3])
                        : "r"(ar[mi][0]), "r"(ar[mi][1]), "r"(ar[mi][2]), "r"(ar[mi][3]),
                          "r"(br[ni][0]), "r"(br[ni][1]));
                }
        }
        bar_post(4 + s);                              // signal slot empty
    }

    // epilogue: partial 128x128 tile -> contiguous plane (pair*SPLITS + split)
    float* pl = g_part + (size_t)(pair * SPLITS + split) * 16384;
    #pragma unroll
    for (int mi = 0; mi < 4; mi++) {
        const int r = 64 * wr + 16 * mi + g;
        #pragma unroll
        for (int ni = 0; ni < 4; ni++) {
            const int c = 32 * wc + 8 * ni + 2 * t;
            *(float2*)(pl + r * 128 + c)       = make_float2(acc[mi][ni][0], acc[mi][ni][1]);
            *(float2*)(pl + (r + 8) * 128 + c) = make_float2(acc[mi][ni][2], acc[mi][ni][3]);
        }
    }
}

// Sum 14 contiguous planes per pair; one float per thread; mirror to upper triangle.
__global__ void gram_reduce(float* __restrict__ out) {
    const int idx  = blockIdx.x * blockDim.x + threadIdx.x;   // 0..163839
    const int pair = idx >> 14;
    const int e    = idx & 16383;

    int bi = 0;
    while ((bi + 1) * (bi + 2) / 2 <= pair) bi++;
    const int bj = pair - bi * (bi + 1) / 2;

    const float* base = g_part + (size_t)pair * SPLITS * 16384 + e;
    float s = 0.f;
    #pragma unroll
    for (int k = 0; k < SPLITS; k++)
        s += base[k * 16384];

    const int r = e >> 7, c = e & 127;
    const int gi = bi * BM + r, gj = bj * BM + c;
    out[(size_t)gi * CD + gj] = s;
    out[(size_t)gj * CD + gi] = s;
}

extern "C" void kernel_launch(void* const* d_in, const int* in_sizes, int n_in,
                              void* d_out, int out_size) {
    const float* x = (const float*)d_in[0];   // [1,512,256,256] = [512, 65536]
    float* out = (float*)d_out;               // [1,1,512,512]

    cudaFuncSetAttribute(gram_fused, cudaFuncAttributeMaxDynamicSharedMemorySize, SMEM_BYTES);
    gram_fused<<<NPAIRS * SPLITS, THREADS, SMEM_BYTES>>>(x);
    gram_reduce<<<NPAIRS * 64, 256>>>(out);
}